// round 1
// baseline (speedup 1.0000x reference)
#include <cuda_runtime.h>
#include <math.h>

#define BB 4
#define SS 2048
#define DD 512

// Scratch (no allocations allowed) -----------------------------------------
__device__ float g_q[BB*SS*DD];
__device__ float g_k[BB*SS*DD];
__device__ float g_v[BB*SS*DD];
__device__ float g_qn2[BB*SS];
__device__ float g_kn2[BB*SS];
__device__ float g_scores[(size_t)BB*SS*SS];
__device__ float g_attn_fb[(size_t)BB*SS*SS];   // fallback if d_out has no attn region

__device__ __forceinline__ void curv_params(const float* __restrict__ craw,
                                            float& kval, float& absk, float& sk, int& branch) {
    float k = -2.0f + 2.0f * (tanhf(craw[0]) + 1.0f);   // k_min + (k_max-k_min)*(tanh+1)/2
    kval = k;
    absk = fabsf(k);
    sk = sqrtf(fmaxf(absk, 1e-5f));
    branch = (absk < 0.01f) ? 0 : ((k < 0.0f) ? 1 : 2);  // 0=euclid 1=hyp 2=sph
}

// --------------------------------------------------------------------------
// QKV: out[m,n] = sum_d x[m,d]*W[n,d] + b[n]   (NT GEMM, M=8192,N=512,K=512)
// --------------------------------------------------------------------------
__global__ __launch_bounds__(256)
void qkv_kernel(const float* __restrict__ x,
                const float* __restrict__ Wq, const float* __restrict__ bq,
                const float* __restrict__ Wk, const float* __restrict__ bk,
                const float* __restrict__ Wv, const float* __restrict__ bv) {
    const int K = DD;
    const float* W; const float* bias; float* out;
    if (blockIdx.z == 0)      { W = Wq; bias = bq; out = g_q; }
    else if (blockIdx.z == 1) { W = Wk; bias = bk; out = g_k; }
    else                      { W = Wv; bias = bv; out = g_v; }

    __shared__ float As[16][68];
    __shared__ float Bs[16][68];
    const int bm = blockIdx.y * 64, bn = blockIdx.x * 64;
    const int t = threadIdx.x;
    const int tx = t & 15, ty = t >> 4;
    const int lr = t >> 2;          // 0..63
    const int lc = (t & 3) * 4;     // 0,4,8,12

    float acc[4][4] = {};
    for (int k0 = 0; k0 < K; k0 += 16) {
        float4 av = *(const float4*)&x[(size_t)(bm + lr) * K + k0 + lc];
        float4 bw = *(const float4*)&W[(size_t)(bn + lr) * K + k0 + lc];
        __syncthreads();
        As[lc+0][lr] = av.x; As[lc+1][lr] = av.y; As[lc+2][lr] = av.z; As[lc+3][lr] = av.w;
        Bs[lc+0][lr] = bw.x; Bs[lc+1][lr] = bw.y; Bs[lc+2][lr] = bw.z; Bs[lc+3][lr] = bw.w;
        __syncthreads();
        #pragma unroll
        for (int kk = 0; kk < 16; kk++) {
            float4 a4 = *(const float4*)&As[kk][ty * 4];
            float4 b4 = *(const float4*)&Bs[kk][tx * 4];
            float ar[4] = {a4.x, a4.y, a4.z, a4.w};
            float br[4] = {b4.x, b4.y, b4.z, b4.w};
            #pragma unroll
            for (int i = 0; i < 4; i++)
                #pragma unroll
                for (int j = 0; j < 4; j++)
                    acc[i][j] += ar[i] * br[j];
        }
    }
    #pragma unroll
    for (int i = 0; i < 4; i++) {
        int m = bm + ty * 4 + i;
        #pragma unroll
        for (int j = 0; j < 4; j++) {
            int n = bn + tx * 4 + j;
            out[(size_t)m * DD + n] = acc[i][j] + bias[n];
        }
    }
}

// --------------------------------------------------------------------------
// Projection: in-place project rows of g_q / g_k, record projected |.|^2
// --------------------------------------------------------------------------
__global__ __launch_bounds__(128)
void project_kernel(const float* __restrict__ craw) {
    float kval, absk, sk; int branch;
    curv_params(craw, kval, absk, sk, branch);

    const int row = blockIdx.x;
    float* buf   = (blockIdx.y == 0) ? g_q  : g_k;
    float* n2out = (blockIdx.y == 0) ? g_qn2 : g_kn2;
    float* p = buf + (size_t)row * DD;
    const int t = threadIdx.x;

    float v4[4]; float s = 0.f;
    #pragma unroll
    for (int u = 0; u < 4; u++) { v4[u] = p[t + u * 128]; s += v4[u] * v4[u]; }

    __shared__ float red[4];
    #pragma unroll
    for (int o = 16; o > 0; o >>= 1) s += __shfl_xor_sync(0xffffffffu, s, o);
    if ((t & 31) == 0) red[t >> 5] = s;
    __syncthreads();
    float sum;
    {
        float r0 = red[0] + red[1] + red[2] + red[3];
        sum = r0;
    }

    float scale;
    if (branch == 0) {
        scale = 1.0f;
    } else if (branch == 1) {
        float n = sqrtf(sum + 1e-12f);
        float mx = (1.0f - 1e-3f) / sk;
        scale = fminf(1.0f, mx / n);
    } else {
        float n = sqrtf(sum + 1e-12f);
        scale = 1.0f / (n * sk);
    }
    #pragma unroll
    for (int u = 0; u < 4; u++) p[t + u * 128] = v4[u] * scale;
    if (t == 0) n2out[row] = sum * scale * scale;
}

// --------------------------------------------------------------------------
// Scores: per batch, S_ij = -dist(qm_i, km_j)/T   (NT GEMM + distance epilogue)
// Causal: blocks fully above the diagonal are skipped (softmax never reads them)
// --------------------------------------------------------------------------
__global__ __launch_bounds__(256)
void score_kernel(const float* __restrict__ craw, const float* __restrict__ temp) {
    const int b = blockIdx.z;
    const int bm = blockIdx.y * 64, bn = blockIdx.x * 64;
    if (bn > bm + 63) return;   // causal skip

    float kval, absk, sk; int branch;
    curv_params(craw, kval, absk, sk, branch);

    const float* A  = g_q + (size_t)b * SS * DD;
    const float* Bm = g_k + (size_t)b * SS * DD;

    __shared__ float As[16][68];
    __shared__ float Bs[16][68];
    const int t = threadIdx.x;
    const int tx = t & 15, ty = t >> 4;
    const int lr = t >> 2;
    const int lc = (t & 3) * 4;

    float acc[4][4] = {};
    for (int k0 = 0; k0 < DD; k0 += 16) {
        float4 av = *(const float4*)&A [(size_t)(bm + lr) * DD + k0 + lc];
        float4 bw = *(const float4*)&Bm[(size_t)(bn + lr) * DD + k0 + lc];
        __syncthreads();
        As[lc+0][lr] = av.x; As[lc+1][lr] = av.y; As[lc+2][lr] = av.z; As[lc+3][lr] = av.w;
        Bs[lc+0][lr] = bw.x; Bs[lc+1][lr] = bw.y; Bs[lc+2][lr] = bw.z; Bs[lc+3][lr] = bw.w;
        __syncthreads();
        #pragma unroll
        for (int kk = 0; kk < 16; kk++) {
            float4 a4 = *(const float4*)&As[kk][ty * 4];
            float4 b4 = *(const float4*)&Bs[kk][tx * 4];
            float ar[4] = {a4.x, a4.y, a4.z, a4.w};
            float br[4] = {b4.x, b4.y, b4.z, b4.w};
            #pragma unroll
            for (int i = 0; i < 4; i++)
                #pragma unroll
                for (int j = 0; j < 4; j++)
                    acc[i][j] += ar[i] * br[j];
        }
    }

    const float invT = 1.0f / (temp[0] + 1e-8f);
    const float* qn2 = g_qn2 + b * SS;
    const float* kn2 = g_kn2 + b * SS;
    float* out = g_scores + (size_t)b * SS * SS;

    #pragma unroll
    for (int i = 0; i < 4; i++) {
        int m = bm + ty * 4 + i;
        float qq = qn2[m];
        #pragma unroll
        for (int j = 0; j < 4; j++) {
            int n = bn + tx * 4 + j;
            float dot = acc[i][j];
            float kn = kn2[n];
            float dist;
            if (branch == 0) {
                float d2 = fmaxf(qq + kn - 2.0f * dot, 0.0f);
                dist = sqrtf(d2 + 1e-12f);
            } else if (branch == 1) {
                float d2 = fmaxf(qq + kn - 2.0f * dot, 0.0f);
                float den = fmaxf((1.0f - absk * qq) * (1.0f - absk * kn), 1e-5f);
                float arg = 1.0f + 2.0f * absk * d2 / den;
                dist = acoshf(fmaxf(arg, 1.0f + 1e-7f)) / sk;
            } else {
                float c = fminf(fmaxf(absk * dot, -1.0f + 1e-7f), 1.0f - 1e-7f);
                dist = acosf(c) / sk;
            }
            out[(size_t)m * SS + n] = -dist * invT;
        }
    }
}

// --------------------------------------------------------------------------
// Causal row softmax: attn[row][j] = softmax over j<=i, zeros for j>i
// --------------------------------------------------------------------------
__global__ __launch_bounds__(256)
void softmax_kernel(float* __restrict__ attn) {
    const int row = blockIdx.x;        // b*S + i
    const int i = row & (SS - 1);
    const float* s = g_scores + (size_t)row * SS;
    float* a = attn + (size_t)row * SS;
    const int t = threadIdx.x;

    float vals[8];
    float mx = -1e30f;
    #pragma unroll
    for (int u = 0; u < 8; u++) {
        int j = t + u * 256;
        vals[u] = (j <= i) ? s[j] : -1e30f;
        mx = fmaxf(mx, vals[u]);
    }

    __shared__ float red[8];
    #pragma unroll
    for (int o = 16; o > 0; o >>= 1) mx = fmaxf(mx, __shfl_xor_sync(0xffffffffu, mx, o));
    if ((t & 31) == 0) red[t >> 5] = mx;
    __syncthreads();
    mx = red[0];
    #pragma unroll
    for (int w = 1; w < 8; w++) mx = fmaxf(mx, red[w]);
    __syncthreads();

    float sum = 0.f;
    #pragma unroll
    for (int u = 0; u < 8; u++) {
        int j = t + u * 256;
        float e = (j <= i) ? expf(vals[u] - mx) : 0.0f;
        vals[u] = e;
        sum += e;
    }
    #pragma unroll
    for (int o = 16; o > 0; o >>= 1) sum += __shfl_xor_sync(0xffffffffu, sum, o);
    if ((t & 31) == 0) red[t >> 5] = sum;
    __syncthreads();
    float tot = 0.f;
    #pragma unroll
    for (int w = 0; w < 8; w++) tot += red[w];
    float inv = 1.0f / tot;

    #pragma unroll
    for (int u = 0; u < 8; u++) {
        int j = t + u * 256;
        a[j] = vals[u] * inv;          // zeros for j > i
    }
}

// --------------------------------------------------------------------------
// Output: out[b,i,d] = sum_j attn[b,i,j] * v[b,j,d]   (NN GEMM, K truncated
// at the diagonal since attn is zero above it)
// --------------------------------------------------------------------------
__global__ __launch_bounds__(256)
void out_kernel(const float* __restrict__ attn, float* __restrict__ out) {
    const int b = blockIdx.z;
    const int bm = blockIdx.y * 64, bn = blockIdx.x * 64;
    const float* A  = attn + (size_t)b * SS * SS;
    const float* Bv = g_v  + (size_t)b * SS * DD;

    __shared__ float As[16][68];
    __shared__ float Bs[16][64];
    const int t = threadIdx.x;
    const int tx = t & 15, ty = t >> 4;
    const int lr = t >> 2;          // A: 0..63 rows
    const int lc = (t & 3) * 4;     // A: k offset
    const int vr = t >> 4;          // B: 0..15 rows (k)
    const int vc = (t & 15) * 4;    // B: 0..60 cols (d)

    float acc[4][4] = {};
    const int kmax = bm + 64;       // causal: attn zero beyond diagonal block
    for (int k0 = 0; k0 < kmax; k0 += 16) {
        float4 av = *(const float4*)&A [(size_t)(bm + lr) * SS + k0 + lc];
        float4 bw = *(const float4*)&Bv[(size_t)(k0 + vr) * DD + bn + vc];
        __syncthreads();
        As[lc+0][lr] = av.x; As[lc+1][lr] = av.y; As[lc+2][lr] = av.z; As[lc+3][lr] = av.w;
        *(float4*)&Bs[vr][vc] = bw;
        __syncthreads();
        #pragma unroll
        for (int kk = 0; kk < 16; kk++) {
            float4 a4 = *(const float4*)&As[kk][ty * 4];
            float4 b4 = *(const float4*)&Bs[kk][tx * 4];
            float ar[4] = {a4.x, a4.y, a4.z, a4.w};
            float br[4] = {b4.x, b4.y, b4.z, b4.w};
            #pragma unroll
            for (int i = 0; i < 4; i++)
                #pragma unroll
                for (int j = 0; j < 4; j++)
                    acc[i][j] += ar[i] * br[j];
        }
    }
    #pragma unroll
    for (int i = 0; i < 4; i++) {
        int m = bm + ty * 4 + i;
        #pragma unroll
        for (int j = 0; j < 4; j++) {
            int n = bn + tx * 4 + j;
            out[(size_t)b * SS * DD + (size_t)m * DD + n] = acc[i][j];
        }
    }
}

// --------------------------------------------------------------------------
extern "C" void kernel_launch(void* const* d_in, const int* in_sizes, int n_in,
                              void* d_out, int out_size) {
    const float* x    = (const float*)d_in[0];
    const float* Wq   = (const float*)d_in[1];
    const float* bq   = (const float*)d_in[2];
    const float* Wk   = (const float*)d_in[3];
    const float* bk   = (const float*)d_in[4];
    const float* Wv   = (const float*)d_in[5];
    const float* bv   = (const float*)d_in[6];
    const float* craw = (const float*)d_in[7];
    const float* temp = (const float*)d_in[8];
    // d_in[9] = mask: fixed causal triu -> implemented structurally

    float* out = (float*)d_out;
    const size_t out_elems = (size_t)BB * SS * DD;
    const size_t attn_elems = (size_t)BB * SS * SS;

    float* attn_ptr;
    if ((size_t)out_size >= out_elems + attn_elems) {
        attn_ptr = out + out_elems;             // write attention straight into d_out
    } else {
        void* p = nullptr;
        cudaGetSymbolAddress(&p, g_attn_fb);    // fallback scratch (no allocation)
        attn_ptr = (float*)p;
    }

    qkv_kernel<<<dim3(DD / 64, (BB * SS) / 64, 3), 256>>>(x, Wq, bq, Wk, bk, Wv, bv);
    project_kernel<<<dim3(BB * SS, 2), 128>>>(craw);
    score_kernel<<<dim3(SS / 64, SS / 64, BB), 256>>>(craw, temp);
    softmax_kernel<<<BB * SS, 256>>>(attn_ptr);
    out_kernel<<<dim3(DD / 64, SS / 64, BB), 256>>>(attn_ptr, out);
}

// round 5
// speedup vs baseline: 1.2357x; 1.2357x over previous
#include <cuda_runtime.h>
#include <cuda_bf16.h>
#include <cstdint>
#include <math.h>

#define BB 4
#define SS 2048
#define DD 512

// ---------------------------------------------------------------------------
// Scratch globals (no allocations allowed)
// ---------------------------------------------------------------------------
__device__ __nv_bfloat16 g_xh[BB*SS*DD], g_xl[BB*SS*DD];
__device__ __nv_bfloat16 g_Wh[3][DD*DD], g_Wl[3][DD*DD];
__device__ float g_q[BB*SS*DD], g_k[BB*SS*DD];
__device__ float g_qn2[BB*SS], g_kn2[BB*SS];
__device__ __nv_bfloat16 g_qmh[BB*SS*DD], g_qml[BB*SS*DD];
__device__ __nv_bfloat16 g_kmh[BB*SS*DD], g_kml[BB*SS*DD];
__device__ __nv_bfloat16 g_vTh[BB*DD*SS], g_vTl[BB*DD*SS];
__device__ float g_scores[(size_t)BB*SS*SS];
__device__ __nv_bfloat16 g_ah[(size_t)BB*SS*SS], g_al[(size_t)BB*SS*SS];
__device__ float g_attn_fb[(size_t)BB*SS*SS];

// ---------------------------------------------------------------------------
__device__ __forceinline__ uint32_t smem_u32(const void* p) {
    uint32_t a;
    asm("{ .reg .u64 t; cvta.to.shared.u64 t, %1; cvt.u32.u64 %0, t; }" : "=r"(a) : "l"(p));
    return a;
}

__device__ __forceinline__ void ldsm_x4(uint32_t* r, uint32_t addr) {
    asm volatile("ldmatrix.sync.aligned.m8n8.x4.shared.b16 {%0,%1,%2,%3}, [%4];"
        : "=r"(r[0]), "=r"(r[1]), "=r"(r[2]), "=r"(r[3]) : "r"(addr));
}

__device__ __forceinline__ void mma_bf16(float* d, const uint32_t* a, const uint32_t* b) {
    asm volatile("mma.sync.aligned.m16n8k16.row.col.f32.bf16.bf16.f32 "
        "{%0,%1,%2,%3}, {%4,%5,%6,%7}, {%8,%9}, {%0,%1,%2,%3};"
        : "+f"(d[0]), "+f"(d[1]), "+f"(d[2]), "+f"(d[3])
        : "r"(a[0]), "r"(a[1]), "r"(a[2]), "r"(a[3]), "r"(b[0]), "r"(b[1]));
}

__device__ __forceinline__ void curv_params(const float* __restrict__ craw,
                                            float& kval, float& absk, float& sk, int& branch) {
    float k = -2.0f + 2.0f * (tanhf(craw[0]) + 1.0f);
    kval = k;
    absk = fabsf(k);
    sk = sqrtf(fmaxf(absk, 1e-5f));
    branch = (absk < 0.01f) ? 0 : ((k < 0.0f) ? 1 : 2);
}

// ---------------------------------------------------------------------------
// Tensor-core GEMM (mma.sync bf16, error-compensated hi/lo split).
// 512 threads, CTA tile 128x128, warp tile 32x32 (4x4 warps), K-chunk 32.
// MODE: 0 = QKV (z picks Q/K/V), 1 = scores, 2 = attn @ V
// ---------------------------------------------------------------------------
#define LDT 40              // smem row stride in bf16 (80B, conflict-free for ldmatrix)

template<int MODE>
__global__ __launch_bounds__(512)
void gemm_tc(const float* __restrict__ bq, const float* __restrict__ bk,
             const float* __restrict__ bv,
             const float* __restrict__ craw, const float* __restrict__ temp,
             float* __restrict__ outp) {
    if (MODE == 1 && blockIdx.x > blockIdx.y) return;   // causal tile skip

    __shared__ __align__(16) __nv_bfloat16 smA[2][128 * LDT];  // [hi/lo]
    __shared__ __align__(16) __nv_bfloat16 smB[2][128 * LDT];

    const int tid  = threadIdx.x;
    const int wid  = tid >> 5;
    const int lane = tid & 31;
    const int wm   = wid >> 2;       // 0..3 -> rows wm*32..+31
    const int wn   = wid & 3;        // 0..3 -> cols wn*32..+31
    const int m0   = blockIdx.y * 128;
    const int n0   = blockIdx.x * 128;
    const int z    = blockIdx.z;

    const __nv_bfloat16 *gAh, *gAl, *gBh, *gBl;
    int ldA, ldB, kChunks;
    if (MODE == 0) {
        gAh = g_xh; gAl = g_xl; gBh = g_Wh[z]; gBl = g_Wl[z];
        ldA = DD; ldB = DD; kChunks = DD / 32;
    } else if (MODE == 1) {
        size_t bo = (size_t)z * SS * DD;
        gAh = g_qmh + bo; gAl = g_qml + bo; gBh = g_kmh + bo; gBl = g_kml + bo;
        ldA = DD; ldB = DD; kChunks = DD / 32;
    } else {
        gAh = g_ah + (size_t)z * SS * SS; gAl = g_al + (size_t)z * SS * SS;
        gBh = g_vTh + (size_t)z * DD * SS; gBl = g_vTl + (size_t)z * DD * SS;
        ldA = SS; ldB = SS; kChunks = 4 * (blockIdx.y + 1);   // causal K truncation
    }

    const uint32_t uAh = smem_u32(smA[0]), uAl = smem_u32(smA[1]);
    const uint32_t uBh = smem_u32(smB[0]), uBl = smem_u32(smB[1]);

    float acc[2][4][4] = {};   // warp tile 32x32: 2 m16-tiles x 4 n8-tiles

    // ldmatrix lane offsets
    const int a_row = lane & 15;                 // + i*16
    const int a_ko  = (lane >> 4) << 3;
    const int b_row = (lane & 7) + ((lane >> 4) << 3);  // + p*16
    const int b_ko  = ((lane >> 3) & 1) << 3;

    for (int ch = 0; ch < kChunks; ++ch) {
        const int k0 = ch * 32;
        // load 4 tiles (Ah, Al, Bh, Bl), each 128x32 bf16
        #pragma unroll
        for (int it = 0; it < 2; ++it) {
            int idx = it * 512 + tid;
            int r = idx >> 3, g = idx & 7;
            uint32_t so = (uint32_t)(r * LDT + g * 4) * 2;
            size_t ga = (size_t)(m0 + r) * ldA + k0 + g * 4;
            size_t gb = (size_t)(n0 + r) * ldB + k0 + g * 4;
            *(uint2*)((char*)smA[0] + so) = *(const uint2*)(gAh + ga);
            *(uint2*)((char*)smA[1] + so) = *(const uint2*)(gAl + ga);
            *(uint2*)((char*)smB[0] + so) = *(const uint2*)(gBh + gb);
            *(uint2*)((char*)smB[1] + so) = *(const uint2*)(gBl + gb);
        }
        __syncthreads();

        #pragma unroll
        for (int ks = 0; ks < 2; ++ks) {
            const int kb = ks * 16;
            uint32_t ah[2][4], al[2][4], bh[4][2], bl[4][2];
            #pragma unroll
            for (int i = 0; i < 2; ++i) {
                uint32_t off = (uint32_t)((wm * 32 + i * 16 + a_row) * LDT + kb + a_ko) * 2;
                ldsm_x4(ah[i], uAh + off);
                ldsm_x4(al[i], uAl + off);
            }
            #pragma unroll
            for (int p = 0; p < 2; ++p) {
                uint32_t off = (uint32_t)((wn * 32 + p * 16 + b_row) * LDT + kb + b_ko) * 2;
                uint32_t rh[4], rl[4];
                ldsm_x4(rh, uBh + off);
                ldsm_x4(rl, uBl + off);
                bh[p*2][0] = rh[0]; bh[p*2][1] = rh[1]; bh[p*2+1][0] = rh[2]; bh[p*2+1][1] = rh[3];
                bl[p*2][0] = rl[0]; bl[p*2][1] = rl[1]; bl[p*2+1][0] = rl[2]; bl[p*2+1][1] = rl[3];
            }
            #pragma unroll
            for (int i = 0; i < 2; ++i)
                #pragma unroll
                for (int j = 0; j < 4; ++j) {
                    mma_bf16(acc[i][j], ah[i], bh[j]);
                    mma_bf16(acc[i][j], ah[i], bl[j]);
                    mma_bf16(acc[i][j], al[i], bh[j]);
                }
        }
        __syncthreads();
    }

    // ---- epilogue: 4 passes of 32 rows staged through smem ----
    float (*stage)[133] = (float (*)[133])smA;   // 32*133*4 = 17KB, fits in smA

    float kv, absk, sk; int branch;
    float invT = 1.0f;
    if (MODE == 1) {
        curv_params(craw, kv, absk, sk, branch);
        invT = 1.0f / (temp[0] + 1e-8f);
    }
    const float* bias = (MODE == 0) ? ((z == 0) ? bq : (z == 1) ? bk : bv) : nullptr;

    #pragma unroll 1
    for (int h = 0; h < 4; ++h) {
        __syncthreads();
        if (wm == h) {
            #pragma unroll
            for (int i = 0; i < 2; ++i)
                #pragma unroll
                for (int j = 0; j < 4; ++j) {
                    int r = i * 16 + (lane >> 2);
                    int c = wn * 32 + j * 8 + 2 * (lane & 3);
                    stage[r][c]     = acc[i][j][0];
                    stage[r][c+1]   = acc[i][j][1];
                    stage[r+8][c]   = acc[i][j][2];
                    stage[r+8][c+1] = acc[i][j][3];
                }
        }
        __syncthreads();

        if (MODE == 0 && z == 2) {
            // V: write transposed bf16 split vT[b][d][j]
            #pragma unroll 2
            for (int it = 0; it < 8; ++it) {
                int idx = it * 512 + tid;
                int rr = idx & 31, cc = idx >> 5;
                float v = stage[rr][cc] + bias[n0 + cc];
                int m = m0 + h * 32 + rr, b = m >> 11, j = m & (SS - 1);
                __nv_bfloat16 hi = __float2bfloat16(v);
                size_t o = ((size_t)b * DD + n0 + cc) * SS + j;
                g_vTh[o] = hi;
                g_vTl[o] = __float2bfloat16(v - __bfloat162float(hi));
            }
        } else if (MODE == 0) {
            float* dst = (z == 0) ? g_q : g_k;
            #pragma unroll 2
            for (int it = 0; it < 8; ++it) {
                int idx = it * 512 + tid;
                int rr = idx >> 7, cc = idx & 127;
                float v = stage[rr][cc] + bias[n0 + cc];
                dst[(size_t)(m0 + h * 32 + rr) * DD + n0 + cc] = v;
            }
        } else if (MODE == 1) {
            const float* qn2 = g_qn2 + z * SS;
            const float* kn2 = g_kn2 + z * SS;
            float* dst = g_scores + (size_t)z * SS * SS;
            #pragma unroll 2
            for (int it = 0; it < 8; ++it) {
                int idx = it * 512 + tid;
                int rr = idx >> 7, cc = idx & 127;
                float dot = stage[rr][cc];
                float qq = qn2[m0 + h * 32 + rr];
                float kk = kn2[n0 + cc];
                float dist;
                if (branch == 0) {
                    float d2 = fmaxf(qq + kk - 2.0f * dot, 0.0f);
                    dist = sqrtf(d2 + 1e-12f);
                } else if (branch == 1) {
                    float d2 = fmaxf(qq + kk - 2.0f * dot, 0.0f);
                    float den = fmaxf((1.0f - absk * qq) * (1.0f - absk * kk), 1e-5f);
                    float arg = 1.0f + 2.0f * absk * d2 / den;
                    dist = acoshf(fmaxf(arg, 1.0f + 1e-7f)) / sk;
                } else {
                    float c = fminf(fmaxf(absk * dot, -1.0f + 1e-7f), 1.0f - 1e-7f);
                    dist = acosf(c) / sk;
                }
                dst[(size_t)(m0 + h * 32 + rr) * SS + n0 + cc] = -dist * invT;
            }
        } else {
            float* dst = outp + (size_t)z * SS * DD;
            #pragma unroll 2
            for (int it = 0; it < 8; ++it) {
                int idx = it * 512 + tid;
                int rr = idx >> 7, cc = idx & 127;
                dst[(size_t)(m0 + h * 32 + rr) * DD + n0 + cc] = stage[rr][cc];
            }
        }
    }
}

// ---------------------------------------------------------------------------
// fp32 -> bf16 hi/lo split (which: 0=x, 1..3 = Wq/Wk/Wv)
// ---------------------------------------------------------------------------
__global__ __launch_bounds__(256)
void split_kernel(const float* __restrict__ src, int which) {
    int i = blockIdx.x * 256 + threadIdx.x;
    __nv_bfloat16 *h, *l;
    if (which == 0)      { h = g_xh;          l = g_xl; }
    else                 { h = g_Wh[which-1]; l = g_Wl[which-1]; }
    float v = src[i];
    __nv_bfloat16 hi = __float2bfloat16(v);
    h[i] = hi;
    l[i] = __float2bfloat16(v - __bfloat162float(hi));
}

// ---------------------------------------------------------------------------
// Projection: read q/k fp32 rows, project, write bf16 split + |.|^2
// ---------------------------------------------------------------------------
__global__ __launch_bounds__(128)
void project_kernel(const float* __restrict__ craw) {
    float kval, absk, sk; int branch;
    curv_params(craw, kval, absk, sk, branch);

    const int row = blockIdx.x;
    const float* src = ((blockIdx.y == 0) ? g_q : g_k) + (size_t)row * DD;
    __nv_bfloat16* oh = ((blockIdx.y == 0) ? g_qmh : g_kmh) + (size_t)row * DD;
    __nv_bfloat16* ol = ((blockIdx.y == 0) ? g_qml : g_kml) + (size_t)row * DD;
    float* n2out = (blockIdx.y == 0) ? g_qn2 : g_kn2;
    const int t = threadIdx.x;

    float v4[4]; float s = 0.f;
    #pragma unroll
    for (int u = 0; u < 4; u++) { v4[u] = src[t + u * 128]; s += v4[u] * v4[u]; }

    __shared__ float red[4];
    #pragma unroll
    for (int o = 16; o > 0; o >>= 1) s += __shfl_xor_sync(0xffffffffu, s, o);
    if ((t & 31) == 0) red[t >> 5] = s;
    __syncthreads();
    float sum = red[0] + red[1] + red[2] + red[3];

    float scale;
    if (branch == 0) {
        scale = 1.0f;
    } else if (branch == 1) {
        float n = sqrtf(sum + 1e-12f);
        float mx = (1.0f - 1e-3f) / sk;
        scale = fminf(1.0f, mx / n);
    } else {
        float n = sqrtf(sum + 1e-12f);
        scale = 1.0f / (n * sk);
    }
    #pragma unroll
    for (int u = 0; u < 4; u++) {
        float pv = v4[u] * scale;
        __nv_bfloat16 h = __float2bfloat16(pv);
        oh[t + u * 128] = h;
        ol[t + u * 128] = __float2bfloat16(pv - __bfloat162float(h));
    }
    if (t == 0) n2out[row] = sum * scale * scale;
}

// ---------------------------------------------------------------------------
// Causal row softmax -> fp32 attention (d_out) + bf16 split (g_ah/g_al)
// ---------------------------------------------------------------------------
__global__ __launch_bounds__(256)
void softmax_kernel(float* __restrict__ attn) {
    const int row = blockIdx.x;         // b*S + i
    const int i = row & (SS - 1);
    const float* s = g_scores + (size_t)row * SS;
    float* a = attn + (size_t)row * SS;
    __nv_bfloat16* ah = g_ah + (size_t)row * SS;
    __nv_bfloat16* al = g_al + (size_t)row * SS;
    const int t = threadIdx.x;

    float vals[8];
    float mx = -1e30f;
    #pragma unroll
    for (int u = 0; u < 8; u++) {
        int j = t + u * 256;
        vals[u] = (j <= i) ? s[j] : -1e30f;
        mx = fmaxf(mx, vals[u]);
    }

    __shared__ float red[8];
    #pragma unroll
    for (int o = 16; o > 0; o >>= 1) mx = fmaxf(mx, __shfl_xor_sync(0xffffffffu, mx, o));
    if ((t & 31) == 0) red[t >> 5] = mx;
    __syncthreads();
    mx = red[0];
    #pragma unroll
    for (int w = 1; w < 8; w++) mx = fmaxf(mx, red[w]);
    __syncthreads();

    float sum = 0.f;
    #pragma unroll
    for (int u = 0; u < 8; u++) {
        int j = t + u * 256;
        float e = (j <= i) ? expf(vals[u] - mx) : 0.0f;
        vals[u] = e;
        sum += e;
    }
    #pragma unroll
    for (int o = 16; o > 0; o >>= 1) sum += __shfl_xor_sync(0xffffffffu, sum, o);
    if ((t & 31) == 0) red[t >> 5] = sum;
    __syncthreads();
    float tot = 0.f;
    #pragma unroll
    for (int w = 0; w < 8; w++) tot += red[w];
    float inv = 1.0f / tot;

    #pragma unroll
    for (int u = 0; u < 8; u++) {
        int j = t + u * 256;
        float p = vals[u] * inv;
        a[j] = p;
        __nv_bfloat16 h = __float2bfloat16(p);
        ah[j] = h;
        al[j] = __float2bfloat16(p - __bfloat162float(h));
    }
}

// ---------------------------------------------------------------------------
extern "C" void kernel_launch(void* const* d_in, const int* in_sizes, int n_in,
                              void* d_out, int out_size) {
    const float* x    = (const float*)d_in[0];
    const float* Wq   = (const float*)d_in[1];
    const float* bq   = (const float*)d_in[2];
    const float* Wk   = (const float*)d_in[3];
    const float* bk   = (const float*)d_in[4];
    const float* Wv   = (const float*)d_in[5];
    const float* bv   = (const float*)d_in[6];
    const float* craw = (const float*)d_in[7];
    const float* temp = (const float*)d_in[8];

    float* out = (float*)d_out;
    const size_t out_elems = (size_t)BB * SS * DD;
    const size_t attn_elems = (size_t)BB * SS * SS;

    float* attn_ptr;
    if ((size_t)out_size >= out_elems + attn_elems) {
        attn_ptr = out + out_elems;
    } else {
        void* p = nullptr;
        cudaGetSymbolAddress(&p, g_attn_fb);
        attn_ptr = (float*)p;
    }

    split_kernel<<<(BB*SS*DD)/256, 256>>>(x, 0);
    split_kernel<<<(DD*DD)/256, 256>>>(Wq, 1);
    split_kernel<<<(DD*DD)/256, 256>>>(Wk, 2);
    split_kernel<<<(DD*DD)/256, 256>>>(Wv, 3);

    gemm_tc<0><<<dim3(DD/128, (BB*SS)/128, 3), 512>>>(bq, bk, bv, craw, temp, nullptr);
    project_kernel<<<dim3(BB*SS, 2), 128>>>(craw);
    gemm_tc<1><<<dim3(SS/128, SS/128, BB), 512>>>(bq, bk, bv, craw, temp, nullptr);
    softmax_kernel<<<BB*SS, 256>>>(attn_ptr);
    gemm_tc<2><<<dim3(DD/128, SS/128, BB), 512>>>(bq, bk, bv, craw, temp, out);
}

// round 6
// speedup vs baseline: 1.3712x; 1.1096x over previous
#include <cuda_runtime.h>
#include <cuda_bf16.h>
#include <cstdint>
#include <math.h>

#define BB 4
#define SS 2048
#define DD 512

// ---------------------------------------------------------------------------
// Scratch globals (no allocations allowed)
// ---------------------------------------------------------------------------
__device__ __nv_bfloat16 g_xh[BB*SS*DD], g_xl[BB*SS*DD];
__device__ __nv_bfloat16 g_Wh[3][DD*DD], g_Wl[3][DD*DD];
__device__ float g_q[BB*SS*DD], g_k[BB*SS*DD];
__device__ float g_qn2[BB*SS], g_kn2[BB*SS];
__device__ __nv_bfloat16 g_qmh[BB*SS*DD], g_qml[BB*SS*DD];
__device__ __nv_bfloat16 g_kmh[BB*SS*DD], g_kml[BB*SS*DD];
__device__ __nv_bfloat16 g_vTh[BB*DD*SS], g_vTl[BB*DD*SS];
__device__ float g_scores[(size_t)BB*SS*SS];
__device__ __nv_bfloat16 g_ah[(size_t)BB*SS*SS], g_al[(size_t)BB*SS*SS];
__device__ float g_attn_fb[(size_t)BB*SS*SS];

// ---------------------------------------------------------------------------
__device__ __forceinline__ uint32_t smem_u32(const void* p) {
    uint32_t a;
    asm("{ .reg .u64 t; cvta.to.shared.u64 t, %1; cvt.u32.u64 %0, t; }" : "=r"(a) : "l"(p));
    return a;
}

__device__ __forceinline__ void ldsm_x4(uint32_t* r, uint32_t addr) {
    asm volatile("ldmatrix.sync.aligned.m8n8.x4.shared.b16 {%0,%1,%2,%3}, [%4];"
        : "=r"(r[0]), "=r"(r[1]), "=r"(r[2]), "=r"(r[3]) : "r"(addr));
}

__device__ __forceinline__ void mma_bf16(float* d, const uint32_t* a, const uint32_t* b) {
    asm volatile("mma.sync.aligned.m16n8k16.row.col.f32.bf16.bf16.f32 "
        "{%0,%1,%2,%3}, {%4,%5,%6,%7}, {%8,%9}, {%0,%1,%2,%3};"
        : "+f"(d[0]), "+f"(d[1]), "+f"(d[2]), "+f"(d[3])
        : "r"(a[0]), "r"(a[1]), "r"(a[2]), "r"(a[3]), "r"(b[0]), "r"(b[1]));
}

__device__ __forceinline__ void cpa8(uint32_t s, const void* g) {
    asm volatile("cp.async.ca.shared.global [%0], [%1], 8;" :: "r"(s), "l"(g));
}
__device__ __forceinline__ void cpa_commit() {
    asm volatile("cp.async.commit_group;" ::: "memory");
}
template<int N>
__device__ __forceinline__ void cpa_wait() {
    asm volatile("cp.async.wait_group %0;" :: "n"(N) : "memory");
}

__device__ __forceinline__ void curv_params(const float* __restrict__ craw,
                                            float& kval, float& absk, float& sk, int& branch) {
    float k = -2.0f + 2.0f * (tanhf(craw[0]) + 1.0f);
    kval = k;
    absk = fabsf(k);
    sk = sqrtf(fmaxf(absk, 1e-5f));
    branch = (absk < 0.01f) ? 0 : ((k < 0.0f) ? 1 : 2);
}

// ---------------------------------------------------------------------------
// Tensor-core GEMM (mma.sync bf16, error-compensated hi/lo split).
// 512 threads, CTA tile 128x256, warp tile 32x64 (4x4 warps), K-chunk 32,
// cp.async double-buffered mainloop.
// MODE: 0 = QKV (z picks Q/K/V), 1 = scores, 2 = attn @ V
// ---------------------------------------------------------------------------
#define LDT 40                         // smem row stride in bf16 (80B, conflict-free)
#define ABYTES (128 * LDT * 2)         // 10240
#define BBYTES (256 * LDT * 2)         // 20480
#define BUFSZ  (2 * ABYTES + 2 * BBYTES)  // 61440
#define SMEM_DYN (2 * BUFSZ)           // 122880

template<int MODE>
__global__ __launch_bounds__(512)
void gemm_tc(const float* __restrict__ bq, const float* __restrict__ bk,
             const float* __restrict__ bv,
             const float* __restrict__ craw, const float* __restrict__ temp,
             float* __restrict__ outp) {
    const int m0 = blockIdx.y * 128;
    const int n0 = blockIdx.x * 256;
    if (MODE == 1 && n0 > m0 + 127) return;   // causal tile skip

    extern __shared__ __align__(16) char smem[];

    const int tid  = threadIdx.x;
    const int wid  = tid >> 5;
    const int lane = tid & 31;
    const int wm   = wid >> 2;       // 0..3 -> rows wm*32..+31
    const int wn   = wid & 3;        // 0..3 -> cols wn*64..+63
    const int z    = blockIdx.z;

    const __nv_bfloat16 *gAh, *gAl, *gBh, *gBl;
    int ldA, ldB, kChunks;
    if (MODE == 0) {
        gAh = g_xh; gAl = g_xl; gBh = g_Wh[z]; gBl = g_Wl[z];
        ldA = DD; ldB = DD; kChunks = DD / 32;
    } else if (MODE == 1) {
        size_t bo = (size_t)z * SS * DD;
        gAh = g_qmh + bo; gAl = g_qml + bo; gBh = g_kmh + bo; gBl = g_kml + bo;
        ldA = DD; ldB = DD; kChunks = DD / 32;
    } else {
        gAh = g_ah + (size_t)z * SS * SS; gAl = g_al + (size_t)z * SS * SS;
        gBh = g_vTh + (size_t)z * DD * SS; gBl = g_vTl + (size_t)z * DD * SS;
        ldA = SS; ldB = SS; kChunks = 4 * (blockIdx.y + 1);   // causal K truncation
    }

    const uint32_t usm = smem_u32(smem);

    // async chunk loader: A 128x32 (hi+lo), B 256x32 (hi+lo) into buffer `buf`
    auto load_chunk = [&](int buf, int k0) {
        uint32_t ub = usm + buf * BUFSZ;
        #pragma unroll
        for (int it = 0; it < 2; ++it) {          // A: 1024 x 8B ops
            int idx = it * 512 + tid;
            int r = idx >> 3, g = idx & 7;
            uint32_t so = (uint32_t)(r * LDT + g * 4) * 2;
            size_t ga = (size_t)(m0 + r) * ldA + k0 + g * 4;
            cpa8(ub + so, gAh + ga);
            cpa8(ub + ABYTES + so, gAl + ga);
        }
        #pragma unroll
        for (int it = 0; it < 4; ++it) {          // B: 2048 x 8B ops
            int idx = it * 512 + tid;
            int r = idx >> 3, g = idx & 7;
            uint32_t so = (uint32_t)(r * LDT + g * 4) * 2;
            size_t gb = (size_t)(n0 + r) * ldB + k0 + g * 4;
            cpa8(ub + 2 * ABYTES + so, gBh + gb);
            cpa8(ub + 2 * ABYTES + BBYTES + so, gBl + gb);
        }
        cpa_commit();
    };

    float acc[2][8][4] = {};   // warp tile 32x64: 2 m16-tiles x 8 n8-tiles

    // ldmatrix lane offsets
    const int a_row = lane & 15;
    const int a_ko  = (lane >> 4) << 3;
    const int b_row = (lane & 7) + ((lane >> 4) << 3);
    const int b_ko  = ((lane >> 3) & 1) << 3;

    load_chunk(0, 0);

    for (int ch = 0; ch < kChunks; ++ch) {
        const int buf = ch & 1;
        if (ch + 1 < kChunks) load_chunk(buf ^ 1, (ch + 1) * 32);
        if (ch + 1 < kChunks) cpa_wait<1>(); else cpa_wait<0>();
        __syncthreads();

        const uint32_t uAh = usm + buf * BUFSZ;
        const uint32_t uAl = uAh + ABYTES;
        const uint32_t uBh = uAh + 2 * ABYTES;
        const uint32_t uBl = uBh + BBYTES;

        #pragma unroll
        for (int ks = 0; ks < 2; ++ks) {
            const int kb = ks * 16;
            uint32_t ah[2][4], al[2][4];
            #pragma unroll
            for (int i = 0; i < 2; ++i) {
                uint32_t off = (uint32_t)((wm * 32 + i * 16 + a_row) * LDT + kb + a_ko) * 2;
                ldsm_x4(ah[i], uAh + off);
                ldsm_x4(al[i], uAl + off);
            }
            #pragma unroll
            for (int p = 0; p < 4; ++p) {        // p-th n16 block of the 64-wide warp tile
                uint32_t off = (uint32_t)((wn * 64 + p * 16 + b_row) * LDT + kb + b_ko) * 2;
                uint32_t rh[4], rl[4];
                ldsm_x4(rh, uBh + off);
                ldsm_x4(rl, uBl + off);
                uint32_t b0h[2] = {rh[0], rh[1]}, b1h[2] = {rh[2], rh[3]};
                uint32_t b0l[2] = {rl[0], rl[1]}, b1l[2] = {rl[2], rl[3]};
                #pragma unroll
                for (int i = 0; i < 2; ++i) {
                    mma_bf16(acc[i][2*p],   ah[i], b0h);
                    mma_bf16(acc[i][2*p],   ah[i], b0l);
                    mma_bf16(acc[i][2*p],   al[i], b0h);
                    mma_bf16(acc[i][2*p+1], ah[i], b1h);
                    mma_bf16(acc[i][2*p+1], ah[i], b1l);
                    mma_bf16(acc[i][2*p+1], al[i], b1h);
                }
            }
        }
        __syncthreads();   // all reads of buf done before it is refilled
    }

    // ---- epilogue: 4 passes of 32 rows staged through smem ----
    float (*stage)[264] = (float (*)[264])smem;   // 32*264*4 = 33792 B

    float kv, absk, sk; int branch;
    float invT = 1.0f;
    if (MODE == 1) {
        curv_params(craw, kv, absk, sk, branch);
        invT = 1.0f / (temp[0] + 1e-8f);
    }
    const float* bias = (MODE == 0) ? ((z == 0) ? bq : (z == 1) ? bk : bv) : nullptr;

    #pragma unroll 1
    for (int h = 0; h < 4; ++h) {
        __syncthreads();
        if (wm == h) {
            #pragma unroll
            for (int i = 0; i < 2; ++i)
                #pragma unroll
                for (int j = 0; j < 8; ++j) {
                    int r = i * 16 + (lane >> 2);
                    int c = wn * 64 + j * 8 + 2 * (lane & 3);
                    stage[r][c]     = acc[i][j][0];
                    stage[r][c+1]   = acc[i][j][1];
                    stage[r+8][c]   = acc[i][j][2];
                    stage[r+8][c+1] = acc[i][j][3];
                }
        }
        __syncthreads();

        if (MODE == 0 && z == 2) {
            // V: write transposed bf16 split vT[b][d][j]
            #pragma unroll 2
            for (int it = 0; it < 16; ++it) {
                int idx = it * 512 + tid;
                int rr = idx & 31, cc = idx >> 5;       // cc 0..255
                float v = stage[rr][cc] + bias[n0 + cc];
                int m = m0 + h * 32 + rr, b = m >> 11, j = m & (SS - 1);
                __nv_bfloat16 hi = __float2bfloat16(v);
                size_t o = ((size_t)b * DD + n0 + cc) * SS + j;
                g_vTh[o] = hi;
                g_vTl[o] = __float2bfloat16(v - __bfloat162float(hi));
            }
        } else if (MODE == 0) {
            float* dst = (z == 0) ? g_q : g_k;
            #pragma unroll 2
            for (int it = 0; it < 16; ++it) {
                int idx = it * 512 + tid;
                int rr = idx >> 8, cc = idx & 255;
                float v = stage[rr][cc] + bias[n0 + cc];
                dst[(size_t)(m0 + h * 32 + rr) * DD + n0 + cc] = v;
            }
        } else if (MODE == 1) {
            const float* qn2 = g_qn2 + z * SS;
            const float* kn2 = g_kn2 + z * SS;
            float* dst = g_scores + (size_t)z * SS * SS;
            #pragma unroll 2
            for (int it = 0; it < 16; ++it) {
                int idx = it * 512 + tid;
                int rr = idx >> 8, cc = idx & 255;
                float dot = stage[rr][cc];
                float qq = qn2[m0 + h * 32 + rr];
                float kk = kn2[n0 + cc];
                float dist;
                if (branch == 0) {
                    float d2 = fmaxf(qq + kk - 2.0f * dot, 0.0f);
                    dist = sqrtf(d2 + 1e-12f);
                } else if (branch == 1) {
                    float d2 = fmaxf(qq + kk - 2.0f * dot, 0.0f);
                    float den = fmaxf((1.0f - absk * qq) * (1.0f - absk * kk), 1e-5f);
                    float arg = 1.0f + 2.0f * absk * d2 / den;
                    dist = acoshf(fmaxf(arg, 1.0f + 1e-7f)) / sk;
                } else {
                    float c = fminf(fmaxf(absk * dot, -1.0f + 1e-7f), 1.0f - 1e-7f);
                    dist = acosf(c) / sk;
                }
                dst[(size_t)(m0 + h * 32 + rr) * SS + n0 + cc] = -dist * invT;
            }
        } else {
            float* dst = outp + (size_t)z * SS * DD;
            #pragma unroll 2
            for (int it = 0; it < 16; ++it) {
                int idx = it * 512 + tid;
                int rr = idx >> 8, cc = idx & 255;
                dst[(size_t)(m0 + h * 32 + rr) * DD + n0 + cc] = stage[rr][cc];
            }
        }
    }
}

// ---------------------------------------------------------------------------
// fp32 -> bf16 hi/lo split (which: 0=x, 1..3 = Wq/Wk/Wv)
// ---------------------------------------------------------------------------
__global__ __launch_bounds__(256)
void split_kernel(const float* __restrict__ src, int which) {
    int i = blockIdx.x * 256 + threadIdx.x;
    __nv_bfloat16 *h, *l;
    if (which == 0)      { h = g_xh;          l = g_xl; }
    else                 { h = g_Wh[which-1]; l = g_Wl[which-1]; }
    float v = src[i];
    __nv_bfloat16 hi = __float2bfloat16(v);
    h[i] = hi;
    l[i] = __float2bfloat16(v - __bfloat162float(hi));
}

// ---------------------------------------------------------------------------
// Projection: read q/k fp32 rows, project, write bf16 split + |.|^2
// ---------------------------------------------------------------------------
__global__ __launch_bounds__(128)
void project_kernel(const float* __restrict__ craw) {
    float kval, absk, sk; int branch;
    curv_params(craw, kval, absk, sk, branch);

    const int row = blockIdx.x;
    const float* src = ((blockIdx.y == 0) ? g_q : g_k) + (size_t)row * DD;
    __nv_bfloat16* oh = ((blockIdx.y == 0) ? g_qmh : g_kmh) + (size_t)row * DD;
    __nv_bfloat16* ol = ((blockIdx.y == 0) ? g_qml : g_kml) + (size_t)row * DD;
    float* n2out = (blockIdx.y == 0) ? g_qn2 : g_kn2;
    const int t = threadIdx.x;

    float v4[4]; float s = 0.f;
    #pragma unroll
    for (int u = 0; u < 4; u++) { v4[u] = src[t + u * 128]; s += v4[u] * v4[u]; }

    __shared__ float red[4];
    #pragma unroll
    for (int o = 16; o > 0; o >>= 1) s += __shfl_xor_sync(0xffffffffu, s, o);
    if ((t & 31) == 0) red[t >> 5] = s;
    __syncthreads();
    float sum = red[0] + red[1] + red[2] + red[3];

    float scale;
    if (branch == 0) {
        scale = 1.0f;
    } else if (branch == 1) {
        float n = sqrtf(sum + 1e-12f);
        float mx = (1.0f - 1e-3f) / sk;
        scale = fminf(1.0f, mx / n);
    } else {
        float n = sqrtf(sum + 1e-12f);
        scale = 1.0f / (n * sk);
    }
    #pragma unroll
    for (int u = 0; u < 4; u++) {
        float pv = v4[u] * scale;
        __nv_bfloat16 h = __float2bfloat16(pv);
        oh[t + u * 128] = h;
        ol[t + u * 128] = __float2bfloat16(pv - __bfloat162float(h));
    }
    if (t == 0) n2out[row] = sum * scale * scale;
}

// ---------------------------------------------------------------------------
// Causal row softmax -> fp32 attention (d_out) + bf16 split (g_ah/g_al)
// ---------------------------------------------------------------------------
__global__ __launch_bounds__(256)
void softmax_kernel(float* __restrict__ attn) {
    const int row = blockIdx.x;         // b*S + i
    const int i = row & (SS - 1);
    const float* s = g_scores + (size_t)row * SS;
    float* a = attn + (size_t)row * SS;
    __nv_bfloat16* ah = g_ah + (size_t)row * SS;
    __nv_bfloat16* al = g_al + (size_t)row * SS;
    const int t = threadIdx.x;

    float vals[8];
    float mx = -1e30f;
    #pragma unroll
    for (int u = 0; u < 8; u++) {
        int j = t + u * 256;
        vals[u] = (j <= i) ? s[j] : -1e30f;
        mx = fmaxf(mx, vals[u]);
    }

    __shared__ float red[8];
    #pragma unroll
    for (int o = 16; o > 0; o >>= 1) mx = fmaxf(mx, __shfl_xor_sync(0xffffffffu, mx, o));
    if ((t & 31) == 0) red[t >> 5] = mx;
    __syncthreads();
    mx = red[0];
    #pragma unroll
    for (int w = 1; w < 8; w++) mx = fmaxf(mx, red[w]);
    __syncthreads();

    float sum = 0.f;
    #pragma unroll
    for (int u = 0; u < 8; u++) {
        int j = t + u * 256;
        float e = (j <= i) ? expf(vals[u] - mx) : 0.0f;
        vals[u] = e;
        sum += e;
    }
    #pragma unroll
    for (int o = 16; o > 0; o >>= 1) sum += __shfl_xor_sync(0xffffffffu, sum, o);
    if ((t & 31) == 0) red[t >> 5] = sum;
    __syncthreads();
    float tot = 0.f;
    #pragma unroll
    for (int w = 0; w < 8; w++) tot += red[w];
    float inv = 1.0f / tot;

    #pragma unroll
    for (int u = 0; u < 8; u++) {
        int j = t + u * 256;
        float p = vals[u] * inv;
        a[j] = p;
        __nv_bfloat16 h = __float2bfloat16(p);
        ah[j] = h;
        al[j] = __float2bfloat16(p - __bfloat162float(h));
    }
}

// ---------------------------------------------------------------------------
extern "C" void kernel_launch(void* const* d_in, const int* in_sizes, int n_in,
                              void* d_out, int out_size) {
    const float* x    = (const float*)d_in[0];
    const float* Wq   = (const float*)d_in[1];
    const float* bq   = (const float*)d_in[2];
    const float* Wk   = (const float*)d_in[3];
    const float* bk   = (const float*)d_in[4];
    const float* Wv   = (const float*)d_in[5];
    const float* bv   = (const float*)d_in[6];
    const float* craw = (const float*)d_in[7];
    const float* temp = (const float*)d_in[8];

    float* out = (float*)d_out;
    const size_t out_elems = (size_t)BB * SS * DD;
    const size_t attn_elems = (size_t)BB * SS * SS;

    float* attn_ptr;
    if ((size_t)out_size >= out_elems + attn_elems) {
        attn_ptr = out + out_elems;
    } else {
        void* p = nullptr;
        cudaGetSymbolAddress(&p, g_attn_fb);
        attn_ptr = (float*)p;
    }

    static int smem_set = 0;
    if (!smem_set) {
        cudaFuncSetAttribute(gemm_tc<0>, cudaFuncAttributeMaxDynamicSharedMemorySize, SMEM_DYN);
        cudaFuncSetAttribute(gemm_tc<1>, cudaFuncAttributeMaxDynamicSharedMemorySize, SMEM_DYN);
        cudaFuncSetAttribute(gemm_tc<2>, cudaFuncAttributeMaxDynamicSharedMemorySize, SMEM_DYN);
        smem_set = 1;
    }

    split_kernel<<<(BB*SS*DD)/256, 256>>>(x, 0);
    split_kernel<<<(DD*DD)/256, 256>>>(Wq, 1);
    split_kernel<<<(DD*DD)/256, 256>>>(Wk, 2);
    split_kernel<<<(DD*DD)/256, 256>>>(Wv, 3);

    gemm_tc<0><<<dim3(DD/256, (BB*SS)/128, 3), 512, SMEM_DYN>>>(bq, bk, bv, craw, temp, nullptr);
    project_kernel<<<dim3(BB*SS, 2), 128>>>(craw);
    gemm_tc<1><<<dim3(SS/256, SS/128, BB), 512, SMEM_DYN>>>(bq, bk, bv, craw, temp, nullptr);
    softmax_kernel<<<BB*SS, 256>>>(attn_ptr);
    gemm_tc<2><<<dim3(DD/256, SS/128, BB), 512, SMEM_DYN>>>(bq, bk, bv, craw, temp, out);
}

// round 7
// speedup vs baseline: 2.3078x; 1.6830x over previous
#include <cuda_runtime.h>
#include <cuda_bf16.h>
#include <cstdint>
#include <math.h>

#define BB 4
#define SS 2048
#define DD 512

// ---------------------------------------------------------------------------
// Scratch globals (no allocations allowed)
// ---------------------------------------------------------------------------
__device__ __nv_bfloat16 g_xh[BB*SS*DD], g_xl[BB*SS*DD];
__device__ __nv_bfloat16 g_Wh[3][DD*DD], g_Wl[3][DD*DD];
__device__ float g_q[BB*SS*DD], g_k[BB*SS*DD];
__device__ float g_qn2[BB*SS], g_kn2[BB*SS];
__device__ __nv_bfloat16 g_qmh[BB*SS*DD], g_qml[BB*SS*DD];
__device__ __nv_bfloat16 g_kmh[BB*SS*DD], g_kml[BB*SS*DD];
__device__ __nv_bfloat16 g_vTh[BB*DD*SS], g_vTl[BB*DD*SS];
__device__ float g_scores[(size_t)BB*SS*SS];
__device__ __nv_bfloat16 g_ah[(size_t)BB*SS*SS], g_al[(size_t)BB*SS*SS];
__device__ float g_attn_fb[(size_t)BB*SS*SS];

// ---------------------------------------------------------------------------
__device__ __forceinline__ uint32_t smem_u32(const void* p) {
    uint32_t a;
    asm("{ .reg .u64 t; cvta.to.shared.u64 t, %1; cvt.u32.u64 %0, t; }" : "=r"(a) : "l"(p));
    return a;
}

__device__ __forceinline__ void ldsm_x4(uint32_t* r, uint32_t addr) {
    asm volatile("ldmatrix.sync.aligned.m8n8.x4.shared.b16 {%0,%1,%2,%3}, [%4];"
        : "=r"(r[0]), "=r"(r[1]), "=r"(r[2]), "=r"(r[3]) : "r"(addr));
}

__device__ __forceinline__ void mma_bf16(float* d, const uint32_t* a, const uint32_t* b) {
    asm volatile("mma.sync.aligned.m16n8k16.row.col.f32.bf16.bf16.f32 "
        "{%0,%1,%2,%3}, {%4,%5,%6,%7}, {%8,%9}, {%0,%1,%2,%3};"
        : "+f"(d[0]), "+f"(d[1]), "+f"(d[2]), "+f"(d[3])
        : "r"(a[0]), "r"(a[1]), "r"(a[2]), "r"(a[3]), "r"(b[0]), "r"(b[1]));
}

__device__ __forceinline__ void cpa16(uint32_t s, const void* g) {
    asm volatile("cp.async.cg.shared.global [%0], [%1], 16;" :: "r"(s), "l"(g));
}
__device__ __forceinline__ void cpa_commit() {
    asm volatile("cp.async.commit_group;" ::: "memory");
}
template<int N>
__device__ __forceinline__ void cpa_wait() {
    asm volatile("cp.async.wait_group %0;" :: "n"(N) : "memory");
}

__device__ __forceinline__ void curv_params(const float* __restrict__ craw,
                                            float& kval, float& absk, float& sk, int& branch) {
    float k = -2.0f + 2.0f * (tanhf(craw[0]) + 1.0f);
    kval = k;
    absk = fabsf(k);
    sk = sqrtf(fmaxf(absk, 1e-5f));
    branch = (absk < 0.01f) ? 0 : ((k < 0.0f) ? 1 : 2);
}

// ---------------------------------------------------------------------------
// Tensor-core GEMM (mma.sync bf16, error-compensated hi/lo split).
// 512 threads, CTA tile 128x256, warp tile 32x64 (4x4 warps), K-chunk 32,
// 16B cp.async, 3-stage pipeline (1 syncthreads per chunk).
// MODE: 0 = QKV (z picks Q/K/V), 1 = scores, 2 = attn @ V
// ---------------------------------------------------------------------------
#define LDT 40                            // smem row stride in bf16 (80B, conflict-free)
#define ABYTES (128 * LDT * 2)            // 10240
#define BBYTES (256 * LDT * 2)            // 20480
#define BUFSZ  (2 * ABYTES + 2 * BBYTES)  // 61440
#define NSTAGE 3
#define SMEM_DYN (NSTAGE * BUFSZ)         // 184320

template<int MODE>
__global__ __launch_bounds__(512)
void gemm_tc(const float* __restrict__ bq, const float* __restrict__ bk,
             const float* __restrict__ bv,
             const float* __restrict__ craw, const float* __restrict__ temp,
             float* __restrict__ outp) {
    const int m0 = blockIdx.y * 128;
    const int n0 = blockIdx.x * 256;
    if (MODE == 1 && n0 > m0 + 127) return;   // causal tile skip

    extern __shared__ __align__(16) char smem[];

    const int tid  = threadIdx.x;
    const int wid  = tid >> 5;
    const int lane = tid & 31;
    const int wm   = wid >> 2;       // 0..3 -> rows wm*32..+31
    const int wn   = wid & 3;        // 0..3 -> cols wn*64..+63
    const int z    = blockIdx.z;

    const __nv_bfloat16 *gAh, *gAl, *gBh, *gBl;
    int ldA, ldB, kChunks;
    if (MODE == 0) {
        gAh = g_xh; gAl = g_xl; gBh = g_Wh[z]; gBl = g_Wl[z];
        ldA = DD; ldB = DD; kChunks = DD / 32;
    } else if (MODE == 1) {
        size_t bo = (size_t)z * SS * DD;
        gAh = g_qmh + bo; gAl = g_qml + bo; gBh = g_kmh + bo; gBl = g_kml + bo;
        ldA = DD; ldB = DD; kChunks = DD / 32;
    } else {
        gAh = g_ah + (size_t)z * SS * SS; gAl = g_al + (size_t)z * SS * SS;
        gBh = g_vTh + (size_t)z * DD * SS; gBl = g_vTl + (size_t)z * DD * SS;
        ldA = SS; ldB = SS; kChunks = 4 * (blockIdx.y + 1);   // causal K truncation
    }

    const uint32_t usm = smem_u32(smem);

    // async chunk loader, 16B ops: A 128x32 (hi+lo), B 256x32 (hi+lo)
    auto load_chunk = [&](int st, int k0) {
        uint32_t ub = usm + st * BUFSZ;
        {   // A: 512 x 16B per tile, one op per thread per tile
            int r = tid >> 2, g = tid & 3;
            uint32_t so = (uint32_t)(r * LDT + g * 8) * 2;
            size_t ga = (size_t)(m0 + r) * ldA + k0 + g * 8;
            cpa16(ub + so, gAh + ga);
            cpa16(ub + ABYTES + so, gAl + ga);
        }
        #pragma unroll
        for (int it = 0; it < 2; ++it) {   // B: 1024 x 16B per tile
            int idx = it * 512 + tid;
            int r = idx >> 2, g = idx & 3;
            uint32_t so = (uint32_t)(r * LDT + g * 8) * 2;
            size_t gb = (size_t)(n0 + r) * ldB + k0 + g * 8;
            cpa16(ub + 2 * ABYTES + so, gBh + gb);
            cpa16(ub + 2 * ABYTES + BBYTES + so, gBl + gb);
        }
        cpa_commit();
    };

    float acc[2][8][4] = {};   // warp tile 32x64: 2 m16-tiles x 8 n8-tiles

    // ldmatrix lane offsets
    const int a_row = lane & 15;
    const int a_ko  = (lane >> 4) << 3;
    const int b_row = (lane & 7) + ((lane >> 4) << 3);
    const int b_ko  = ((lane >> 3) & 1) << 3;

    load_chunk(0, 0);
    load_chunk(1, 32);       // kChunks >= 4 in every mode

    int stage = 0;
    for (int ch = 0; ch < kChunks; ++ch) {
        if (ch + 1 < kChunks) cpa_wait<1>(); else cpa_wait<0>();
        __syncthreads();

        const uint32_t uAh = usm + stage * BUFSZ;
        const uint32_t uAl = uAh + ABYTES;
        const uint32_t uBh = uAh + 2 * ABYTES;
        const uint32_t uBl = uBh + BBYTES;

        #pragma unroll
        for (int ks = 0; ks < 2; ++ks) {
            const int kb = ks * 16;
            uint32_t ah[2][4], al[2][4];
            #pragma unroll
            for (int i = 0; i < 2; ++i) {
                uint32_t off = (uint32_t)((wm * 32 + i * 16 + a_row) * LDT + kb + a_ko) * 2;
                ldsm_x4(ah[i], uAh + off);
                ldsm_x4(al[i], uAl + off);
            }
            #pragma unroll
            for (int p = 0; p < 4; ++p) {
                uint32_t off = (uint32_t)((wn * 64 + p * 16 + b_row) * LDT + kb + b_ko) * 2;
                uint32_t rh[4], rl[4];
                ldsm_x4(rh, uBh + off);
                ldsm_x4(rl, uBl + off);
                uint32_t b0h[2] = {rh[0], rh[1]}, b1h[2] = {rh[2], rh[3]};
                uint32_t b0l[2] = {rl[0], rl[1]}, b1l[2] = {rl[2], rl[3]};
                #pragma unroll
                for (int i = 0; i < 2; ++i) {
                    mma_bf16(acc[i][2*p],   ah[i], b0h);
                    mma_bf16(acc[i][2*p],   ah[i], b0l);
                    mma_bf16(acc[i][2*p],   al[i], b0h);
                    mma_bf16(acc[i][2*p+1], ah[i], b1h);
                    mma_bf16(acc[i][2*p+1], ah[i], b1l);
                    mma_bf16(acc[i][2*p+1], al[i], b1h);
                }
            }
        }

        if (ch + 2 < kChunks) load_chunk((ch + 2) % NSTAGE, (ch + 2) * 32);
        stage = (stage + 1) % NSTAGE;
    }

    // ---- epilogue: 4 passes of 32 rows staged through smem ----
    float (*stg)[264] = (float (*)[264])smem;   // 32*264*4 = 33792 B

    float kv, absk, sk; int branch;
    float invT = 1.0f;
    if (MODE == 1) {
        curv_params(craw, kv, absk, sk, branch);
        invT = 1.0f / (temp[0] + 1e-8f);
    }
    const float* bias = (MODE == 0) ? ((z == 0) ? bq : (z == 1) ? bk : bv) : nullptr;

    #pragma unroll 1
    for (int h = 0; h < 4; ++h) {
        __syncthreads();
        if (wm == h) {
            #pragma unroll
            for (int i = 0; i < 2; ++i)
                #pragma unroll
                for (int j = 0; j < 8; ++j) {
                    int r = i * 16 + (lane >> 2);
                    int c = wn * 64 + j * 8 + 2 * (lane & 3);
                    stg[r][c]     = acc[i][j][0];
                    stg[r][c+1]   = acc[i][j][1];
                    stg[r+8][c]   = acc[i][j][2];
                    stg[r+8][c+1] = acc[i][j][3];
                }
        }
        __syncthreads();

        if (MODE == 0 && z == 2) {
            // V: write transposed bf16 split vT[b][d][j]
            #pragma unroll 2
            for (int it = 0; it < 16; ++it) {
                int idx = it * 512 + tid;
                int rr = idx & 31, cc = idx >> 5;       // cc 0..255
                float v = stg[rr][cc] + bias[n0 + cc];
                int m = m0 + h * 32 + rr, b = m >> 11, j = m & (SS - 1);
                __nv_bfloat16 hi = __float2bfloat16(v);
                size_t o = ((size_t)b * DD + n0 + cc) * SS + j;
                g_vTh[o] = hi;
                g_vTl[o] = __float2bfloat16(v - __bfloat162float(hi));
            }
        } else if (MODE == 0) {
            float* dst = (z == 0) ? g_q : g_k;
            #pragma unroll 2
            for (int it = 0; it < 16; ++it) {
                int idx = it * 512 + tid;
                int rr = idx >> 8, cc = idx & 255;
                float v = stg[rr][cc] + bias[n0 + cc];
                dst[(size_t)(m0 + h * 32 + rr) * DD + n0 + cc] = v;
            }
        } else if (MODE == 1) {
            const float* qn2 = g_qn2 + z * SS;
            const float* kn2 = g_kn2 + z * SS;
            float* dst = g_scores + (size_t)z * SS * SS;
            #pragma unroll 2
            for (int it = 0; it < 16; ++it) {
                int idx = it * 512 + tid;
                int rr = idx >> 8, cc = idx & 255;
                float dot = stg[rr][cc];
                float qq = qn2[m0 + h * 32 + rr];
                float kk = kn2[n0 + cc];
                float dist;
                if (branch == 0) {
                    float d2 = fmaxf(qq + kk - 2.0f * dot, 0.0f);
                    dist = sqrtf(d2 + 1e-12f);
                } else if (branch == 1) {
                    float d2 = fmaxf(qq + kk - 2.0f * dot, 0.0f);
                    float den = fmaxf((1.0f - absk * qq) * (1.0f - absk * kk), 1e-5f);
                    float arg = 1.0f + 2.0f * absk * d2 / den;
                    dist = acoshf(fmaxf(arg, 1.0f + 1e-7f)) / sk;
                } else {
                    float c = fminf(fmaxf(absk * dot, -1.0f + 1e-7f), 1.0f - 1e-7f);
                    dist = acosf(c) / sk;
                }
                dst[(size_t)(m0 + h * 32 + rr) * SS + n0 + cc] = -dist * invT;
            }
        } else {
            float* dst = outp + (size_t)z * SS * DD;
            #pragma unroll 2
            for (int it = 0; it < 16; ++it) {
                int idx = it * 512 + tid;
                int rr = idx >> 8, cc = idx & 255;
                dst[(size_t)(m0 + h * 32 + rr) * DD + n0 + cc] = stg[rr][cc];
            }
        }
    }
}

// ---------------------------------------------------------------------------
// Fused fp32 -> bf16 hi/lo split for x, Wq, Wk, Wv (one launch)
// ---------------------------------------------------------------------------
#define NX (BB*SS*DD)
#define NW (DD*DD)

__global__ __launch_bounds__(256)
void split_all(const float* __restrict__ x, const float* __restrict__ wq,
               const float* __restrict__ wk, const float* __restrict__ wv) {
    int i = blockIdx.x * 256 + threadIdx.x;
    const float* src; __nv_bfloat16 *h, *l; int off;
    if (i < NX)               { src = x;  h = g_xh;    l = g_xl;    off = i; }
    else if (i < NX + NW)     { src = wq; h = g_Wh[0]; l = g_Wl[0]; off = i - NX; }
    else if (i < NX + 2*NW)   { src = wk; h = g_Wh[1]; l = g_Wl[1]; off = i - NX - NW; }
    else                      { src = wv; h = g_Wh[2]; l = g_Wl[2]; off = i - NX - 2*NW; }
    float v = src[off];
    __nv_bfloat16 hi = __float2bfloat16(v);
    h[off] = hi;
    l[off] = __float2bfloat16(v - __bfloat162float(hi));
}

// ---------------------------------------------------------------------------
// Projection: read q/k fp32 rows, project, write bf16 split + |.|^2
// ---------------------------------------------------------------------------
__global__ __launch_bounds__(128)
void project_kernel(const float* __restrict__ craw) {
    float kval, absk, sk; int branch;
    curv_params(craw, kval, absk, sk, branch);

    const int row = blockIdx.x;
    const float* src = ((blockIdx.y == 0) ? g_q : g_k) + (size_t)row * DD;
    __nv_bfloat16* oh = ((blockIdx.y == 0) ? g_qmh : g_kmh) + (size_t)row * DD;
    __nv_bfloat16* ol = ((blockIdx.y == 0) ? g_qml : g_kml) + (size_t)row * DD;
    float* n2out = (blockIdx.y == 0) ? g_qn2 : g_kn2;
    const int t = threadIdx.x;

    float v4[4]; float s = 0.f;
    #pragma unroll
    for (int u = 0; u < 4; u++) { v4[u] = src[t + u * 128]; s += v4[u] * v4[u]; }

    __shared__ float red[4];
    #pragma unroll
    for (int o = 16; o > 0; o >>= 1) s += __shfl_xor_sync(0xffffffffu, s, o);
    if ((t & 31) == 0) red[t >> 5] = s;
    __syncthreads();
    float sum = red[0] + red[1] + red[2] + red[3];

    float scale;
    if (branch == 0) {
        scale = 1.0f;
    } else if (branch == 1) {
        float n = sqrtf(sum + 1e-12f);
        float mx = (1.0f - 1e-3f) / sk;
        scale = fminf(1.0f, mx / n);
    } else {
        float n = sqrtf(sum + 1e-12f);
        scale = 1.0f / (n * sk);
    }
    #pragma unroll
    for (int u = 0; u < 4; u++) {
        float pv = v4[u] * scale;
        __nv_bfloat16 h = __float2bfloat16(pv);
        oh[t + u * 128] = h;
        ol[t + u * 128] = __float2bfloat16(pv - __bfloat162float(h));
    }
    if (t == 0) n2out[row] = sum * scale * scale;
}

// ---------------------------------------------------------------------------
// Causal row softmax -> fp32 attention (d_out) + bf16 split (g_ah/g_al)
// ---------------------------------------------------------------------------
__global__ __launch_bounds__(256)
void softmax_kernel(float* __restrict__ attn) {
    const int row = blockIdx.x;         // b*S + i
    const int i = row & (SS - 1);
    const float* s = g_scores + (size_t)row * SS;
    float* a = attn + (size_t)row * SS;
    __nv_bfloat16* ah = g_ah + (size_t)row * SS;
    __nv_bfloat16* al = g_al + (size_t)row * SS;
    const int t = threadIdx.x;

    float vals[8];
    float mx = -1e30f;
    #pragma unroll
    for (int u = 0; u < 8; u++) {
        int j = t + u * 256;
        vals[u] = (j <= i) ? s[j] : -1e30f;
        mx = fmaxf(mx, vals[u]);
    }

    __shared__ float red[8];
    #pragma unroll
    for (int o = 16; o > 0; o >>= 1) mx = fmaxf(mx, __shfl_xor_sync(0xffffffffu, mx, o));
    if ((t & 31) == 0) red[t >> 5] = mx;
    __syncthreads();
    mx = red[0];
    #pragma unroll
    for (int w = 1; w < 8; w++) mx = fmaxf(mx, red[w]);
    __syncthreads();

    float sum = 0.f;
    #pragma unroll
    for (int u = 0; u < 8; u++) {
        int j = t + u * 256;
        float e = (j <= i) ? expf(vals[u] - mx) : 0.0f;
        vals[u] = e;
        sum += e;
    }
    #pragma unroll
    for (int o = 16; o > 0; o >>= 1) sum += __shfl_xor_sync(0xffffffffu, sum, o);
    if ((t & 31) == 0) red[t >> 5] = sum;
    __syncthreads();
    float tot = 0.f;
    #pragma unroll
    for (int w = 0; w < 8; w++) tot += red[w];
    float inv = 1.0f / tot;

    #pragma unroll
    for (int u = 0; u < 8; u++) {
        int j = t + u * 256;
        float p = vals[u] * inv;
        a[j] = p;
        __nv_bfloat16 h = __float2bfloat16(p);
        ah[j] = h;
        al[j] = __float2bfloat16(p - __bfloat162float(h));
    }
}

// ---------------------------------------------------------------------------
extern "C" void kernel_launch(void* const* d_in, const int* in_sizes, int n_in,
                              void* d_out, int out_size) {
    const float* x    = (const float*)d_in[0];
    const float* Wq   = (const float*)d_in[1];
    const float* bq   = (const float*)d_in[2];
    const float* Wk   = (const float*)d_in[3];
    const float* bk   = (const float*)d_in[4];
    const float* Wv   = (const float*)d_in[5];
    const float* bv   = (const float*)d_in[6];
    const float* craw = (const float*)d_in[7];
    const float* temp = (const float*)d_in[8];

    float* out = (float*)d_out;
    const size_t out_elems = (size_t)BB * SS * DD;
    const size_t attn_elems = (size_t)BB * SS * SS;

    float* attn_ptr;
    if ((size_t)out_size >= out_elems + attn_elems) {
        attn_ptr = out + out_elems;
    } else {
        void* p = nullptr;
        cudaGetSymbolAddress(&p, g_attn_fb);
        attn_ptr = (float*)p;
    }

    cudaFuncSetAttribute(gemm_tc<0>, cudaFuncAttributeMaxDynamicSharedMemorySize, SMEM_DYN);
    cudaFuncSetAttribute(gemm_tc<1>, cudaFuncAttributeMaxDynamicSharedMemorySize, SMEM_DYN);
    cudaFuncSetAttribute(gemm_tc<2>, cudaFuncAttributeMaxDynamicSharedMemorySize, SMEM_DYN);

    split_all<<<(NX + 3*NW)/256, 256>>>(x, Wq, Wk, Wv);
    gemm_tc<0><<<dim3(DD/256, (BB*SS)/128, 3), 512, SMEM_DYN>>>(bq, bk, bv, craw, temp, nullptr);
    project_kernel<<<dim3(BB*SS, 2), 128>>>(craw);
    gemm_tc<1><<<dim3(SS/256, SS/128, BB), 512, SMEM_DYN>>>(bq, bk, bv, craw, temp, nullptr);
    softmax_kernel<<<BB*SS, 256>>>(attn_ptr);
    gemm_tc<2><<<dim3(DD/256, SS/128, BB), 512, SMEM_DYN>>>(bq, bk, bv, craw, temp, out);
}